// round 10
// baseline (speedup 1.0000x reference)
#include <cuda_runtime.h>

#define NN 307
#define DD 64
#define EE 4912
#define TT 288
#define BB 8
#define NODE_BLOCKS 77      // 77*4 = 308 >= 307 nodes, single wave
#define CH 24               // bt-chunk per k_big block (24 | 288: never crosses b)

// ---- scratch (device globals; no allocation allowed) ----
__device__ float g_h[NN * DD];       // layer activations
__device__ float g_p[NN * DD];       // projected features p = h @ W
__device__ float g_ss[NN * 8];       // per-node src scores
__device__ float g_st[NN * 8];       // per-node tgt scores
__device__ float g_hout[NN * DD];    // final GAT output (+b2), read by k_big
__device__ float g_c[TT * DD];       // pe[t,d] + b_val[d]
__device__ int   g_rowptr[NN + 1];   // CSR row pointers (by target)
__device__ int   g_esrc[EE];         // CSR: source node per edge slot

// ==========================================================================
// CSR build (by target), one 512-thread block:
// smem histogram -> Hillis-Steele inclusive scan -> scatter sources.
// ==========================================================================
__global__ void __launch_bounds__(512)
k_csr(const int* __restrict__ ei)
{
    __shared__ int c[512];
    __shared__ int pos[NN];
    int tid = threadIdx.x;
    c[tid] = 0;
    __syncthreads();
    for (int e = tid; e < EE; e += 512)
        atomicAdd(&c[__ldg(&ei[EE + e]) + 1], 1);     // count deg(t) into slot t+1
    __syncthreads();
    // inclusive scan over c[0..511]: c[t] becomes row start of node t
    for (int s = 1; s < 512; s <<= 1) {
        int v = (tid >= s) ? c[tid - s] : 0;
        __syncthreads();
        c[tid] += v;
        __syncthreads();
    }
    if (tid <= NN) g_rowptr[tid] = c[tid];
    if (tid < NN)  pos[tid] = c[tid];
    __syncthreads();
    for (int e = tid; e < EE; e += 512) {
        int t = __ldg(&ei[EE + e]);
        int j = atomicAdd(&pos[t], 1);
        g_esrc[j] = __ldg(&ei[e]);
    }
}

// ==========================================================================
// Gather phase (replaces edge scatter): for node n, dim lane,
//   num = sum_e w_e * p[src_e, lane],  den = sum_e w_e,
//   w_e = exp(leaky_relu(ss[src_e,h] + st[n,h])),  h = lane/F.
// Max-subtraction dropped (activations O(0.1); identical math, validated
// rel_err ~1e-6 since R2). Unroll-4 for MLP; all arrays L2-resident.
// ==========================================================================
template<int H>
__device__ __forceinline__ void gather(int n, int lane, float& num, float& den)
{
    int h = (H == 1) ? 0 : (lane >> 3);
    float stv = g_st[n * H + h];
    int j   = g_rowptr[n];
    int end = g_rowptr[n + 1];
    num = 0.f; den = 0.f;
    for (; j + 4 <= end; j += 4) {
        int s0 = g_esrc[j], s1 = g_esrc[j + 1], s2 = g_esrc[j + 2], s3 = g_esrc[j + 3];
        float e0 = g_ss[s0 * H + h] + stv;
        float e1 = g_ss[s1 * H + h] + stv;
        float e2 = g_ss[s2 * H + h] + stv;
        float e3 = g_ss[s3 * H + h] + stv;
        float p0 = g_p[s0 * DD + lane];
        float p1 = g_p[s1 * DD + lane];
        float p2 = g_p[s2 * DD + lane];
        float p3 = g_p[s3 * DD + lane];
        e0 = e0 > 0.f ? e0 : 0.2f * e0;  float w0 = __expf(e0);
        e1 = e1 > 0.f ? e1 : 0.2f * e1;  float w1 = __expf(e1);
        e2 = e2 > 0.f ? e2 : 0.2f * e2;  float w2 = __expf(e2);
        e3 = e3 > 0.f ? e3 : 0.2f * e3;  float w3 = __expf(e3);
        num += w0 * p0 + w1 * p1 + w2 * p2 + w3 * p3;
        den += w0 + w1 + w2 + w3;
    }
    for (; j < end; j++) {
        int s = g_esrc[j];
        float ev = g_ss[s * H + h] + stv;
        ev = ev > 0.f ? ev : 0.2f * ev;
        float w = __expf(ev);
        num += w * g_p[s * DD + lane];
        den += w;
    }
}

// ==========================================================================
// proj: p = h @ W -> g_p (+smem), scores ss/st. Block = 4 nodes x 64 lanes.
// ==========================================================================
template<int H, int F>
__device__ __forceinline__ void proj(bool act, int n, int sub, int lane,
                                     const float* __restrict__ W,
                                     const float* __restrict__ as_,
                                     const float* __restrict__ at_,
                                     float (*sh)[DD], float (*sp)[DD])
{
    if (act) {
        float p = 0.f;
#pragma unroll
        for (int k = 0; k < DD; k++)
            p += sh[sub][k] * W[k * DD + lane];
        g_p[n * DD + lane] = p;
        sp[sub][lane] = p;
    }
    __syncthreads();
    if (act && lane < H) {
        float ssv = 0.f, stv = 0.f;
#pragma unroll
        for (int f = 0; f < F; f++) {
            float v = sp[sub][lane * F + f];
            ssv += v * as_[lane * F + f];
            stv += v * at_[lane * F + f];
        }
        g_ss[n * H + lane] = ssv;
        g_st[n * H + lane] = stv;
    }
}

// ==========================================================================
// K1: PE table + node embedding + proj/scores for layer 0.
// ==========================================================================
__global__ void __launch_bounds__(256)
k_first(const float* __restrict__ node_f, const float* __restrict__ b_val,
        const float* __restrict__ W_sta, const float* __restrict__ b_sta,
        const float* __restrict__ ada,
        const float* __restrict__ W, const float* __restrict__ as_,
        const float* __restrict__ at_)
{
    __shared__ float sh[4][DD];
    __shared__ float sp[4][DD];
    int tid  = threadIdx.x;
    int sub  = tid >> 6;
    int lane = tid & 63;
    int n    = blockIdx.x * 4 + sub;
    bool act = n < NN;

    // PE table (77*256 = 19712 >= 18432 elements)
    int idx = blockIdx.x * 256 + tid;
    if (idx < TT * DD) {
        int t = idx >> 6, d = idx & 63;
        float freq = __expf((float)(d & ~1) * (-9.210340371976184f / 64.0f));
        float s, c;
        __sincosf((float)t * freq, &s, &c);
        g_c[idx] = ((d & 1) ? c : s) + b_val[d];
    }

    if (act) {
        float acc = b_sta[lane] + ada[n * DD + lane];
#pragma unroll
        for (int k = 0; k < 32; k++)
            acc += node_f[n * 32 + k] * W_sta[k * DD + lane];
        sh[sub][lane] = acc;
        g_h[n * DD + lane] = acc;
    }
    __syncthreads();

    proj<8, 8>(act, n, sub, lane, W, as_, at_, sh, sp);
}

// ==========================================================================
// k_layer: gather layer L (H=8) + finalize (projected skip, ELU) +
// proj for layer L+1.
// ==========================================================================
template<int HO, int FO>
__global__ void __launch_bounds__(256)
k_layer(const float* __restrict__ skipW, const float* __restrict__ b,
        const float* __restrict__ W, const float* __restrict__ as_,
        const float* __restrict__ at_)
{
    __shared__ float sh[4][DD];
    __shared__ float sp[4][DD];
    int tid  = threadIdx.x;
    int sub  = tid >> 6;
    int lane = tid & 63;
    int n    = blockIdx.x * 4 + sub;
    bool act = n < NN;

    if (act) sh[sub][lane] = g_h[n * DD + lane];
    __syncthreads();

    float v = 0.f;
    if (act) {
        float num, den;
        gather<8>(n, lane, num, den);
        v = num / (den + 1e-16f);
        float skip = 0.f;
#pragma unroll
        for (int k = 0; k < DD; k++)
            skip += sh[sub][k] * skipW[k * DD + lane];
        v += skip + b[lane];
        v = v > 0.f ? v : (__expf(v) - 1.f);     // ELU
    }
    __syncthreads();
    if (act) {
        sh[sub][lane] = v;
        g_h[n * DD + lane] = v;
    }
    __syncthreads();

    proj<HO, FO>(act, n, sub, lane, W, as_, at_, sh, sp);
}

// ==========================================================================
// k_fin2: gather layer 2 (H=1) + identity skip + b2 -> g_hout.
// ==========================================================================
__global__ void __launch_bounds__(256)
k_fin2(const float* __restrict__ b2)
{
    int tid  = threadIdx.x;
    int sub  = tid >> 6;
    int lane = tid & 63;
    int n    = blockIdx.x * 4 + sub;
    if (n >= NN) return;

    float num, den;
    gather<1>(n, lane, num, den);
    float v = num / (den + 1e-16f) + g_h[n * DD + lane] + b2[lane];
    g_hout[n * DD + lane] = v;
}

// ==========================================================================
// Big broadcast kernel: out[bt,n,dq] = x[bt,n]*W[dq] + c[t,dq] + h[n,dq].
// Thread owns one (n,dq) column; h/W in registers; streaming stores.
// ==========================================================================
__global__ void __launch_bounds__(256)
k_big(const float* __restrict__ x, const float* __restrict__ Wv,
      float4* __restrict__ out)
{
    int col = blockIdx.x * 256 + threadIdx.x;    // n*16 + dq, 0..4911
    if (col >= NN * 16) return;
    int dq = col & 15;
    int n  = col >> 4;

    float4 hh = ((const float4*)g_hout)[col];
    float4 w  = ((const float4*)Wv)[dq];

    int bt0 = blockIdx.y * CH;
    int t0  = bt0 % TT;                          // CH | TT: no wrap inside chunk

#pragma unroll 4
    for (int i = 0; i < CH; i++) {
        int bt = bt0 + i;
        float  xv = __ldg(&x[bt * NN + n]);
        float4 cc = ((const float4*)g_c)[(t0 + i) * 16 + dq];
        float4 o;
        o.x = fmaf(xv, w.x, cc.x + hh.x);
        o.y = fmaf(xv, w.y, cc.y + hh.y);
        o.z = fmaf(xv, w.z, cc.z + hh.z);
        o.w = fmaf(xv, w.w, cc.w + hh.w);
        __stcs(&out[bt * (NN * 16) + col], o);   // streaming: don't pollute L2
    }
}

extern "C" void kernel_launch(void* const* d_in, const int* in_sizes, int n_in,
                              void* d_out, int out_size)
{
    const float* x       = (const float*)d_in[0];
    const float* node_f  = (const float*)d_in[1];
    const int*   ei      = (const int*)d_in[2];
    // d_in[3] edge_prob unused
    const float* W_val   = (const float*)d_in[4];
    const float* b_val   = (const float*)d_in[5];
    const float* W_sta   = (const float*)d_in[6];
    const float* b_sta   = (const float*)d_in[7];
    const float* ada     = (const float*)d_in[8];
    const float* g0W     = (const float*)d_in[9];
    const float* g0as    = (const float*)d_in[10];
    const float* g0at    = (const float*)d_in[11];
    const float* g0b     = (const float*)d_in[12];
    const float* g1W     = (const float*)d_in[13];
    const float* g1as    = (const float*)d_in[14];
    const float* g1at    = (const float*)d_in[15];
    const float* g1b     = (const float*)d_in[16];
    const float* g2W     = (const float*)d_in[17];
    const float* g2as    = (const float*)d_in[18];
    const float* g2at    = (const float*)d_in[19];
    const float* g2b     = (const float*)d_in[20];
    const float* g0skip  = (const float*)d_in[21];
    const float* g1skip  = (const float*)d_in[22];

    // 1) CSR by target (once per launch; edge structure shared by all layers)
    k_csr<<<1, 512>>>(ei);
    // 2) PE table + node embedding + proj0
    k_first<<<NODE_BLOCKS, 256>>>(node_f, b_val, W_sta, b_sta, ada, g0W, g0as, g0at);
    // 3) gather L0 + fin + proj1 ; gather L1 + fin + proj2
    k_layer<8, 8><<<NODE_BLOCKS, 256>>>(g0skip, g0b, g1W, g1as, g1at);
    k_layer<1, 64><<<NODE_BLOCKS, 256>>>(g1skip, g1b, g2W, g2as, g2at);
    // 4) gather L2 + identity skip + b2 -> g_hout
    k_fin2<<<NODE_BLOCKS, 256>>>(g2b);
    // 5) broadcast add (HBM-store-bound)
    dim3 gb((NN * 16 + 255) / 256, (BB * TT) / CH);   // (20, 96)
    k_big<<<gb, 256>>>(x, W_val, (float4*)d_out);
}

// round 14
// speedup vs baseline: 1.7584x; 1.7584x over previous
#include <cuda_runtime.h>

#define NN 307
#define DD 64
#define EE 4912
#define TT 288
#define BB 8
#define NODE_BLOCKS 77      // 77*4 = 308 >= 307 nodes, single wave
#define CH 24               // bt-chunk per k_big block (24 | 288: never crosses b)

// ---- scratch (device globals; no allocation allowed) ----
__device__ float g_h[NN * DD];      // layer activations (node-private between kernels)
__device__ float g_p[NN * DD];      // projected features p = h @ W
__device__ float g_ss[NN * 8];      // per-node src scores
__device__ float g_st[NN * 8];      // per-node tgt scores
__device__ float g_num[NN * DD];    // softmax-weighted numerator accum
__device__ float g_den[NN * 8];     // softmax denominator accum
__device__ float g_c[TT * DD];      // pe[t,d] + b_val[d]

// ==========================================================================
// Per-node building blocks. Block = 256 threads = 4 nodes (sub, lane).
// ==========================================================================
template<int H, int F>
__device__ __forceinline__ void proj(bool act, int n, int sub, int lane,
                                     const float* __restrict__ W,
                                     const float* __restrict__ as_,
                                     const float* __restrict__ at_,
                                     float (*sh)[DD], float (*sp)[DD])
{
    if (act) {
        float p = 0.f;
#pragma unroll
        for (int k = 0; k < DD; k++)
            p += sh[sub][k] * W[k * DD + lane];
        g_p[n * DD + lane]   = p;
        g_num[n * DD + lane] = 0.f;
        sp[sub][lane] = p;
    }
    __syncthreads();
    if (act && lane < H) {
        float ssv = 0.f, stv = 0.f;
#pragma unroll
        for (int f = 0; f < F; f++) {
            float v = sp[sub][lane * F + f];
            ssv += v * as_[lane * F + f];
            stv += v * at_[lane * F + f];
        }
        g_ss[n * H + lane]  = ssv;
        g_st[n * H + lane]  = stv;
        g_den[n * H + lane] = 0.f;
    }
}

template<int H, int F>
__device__ __forceinline__ float fin_val(int n, int sub, int lane,
                                         const float* __restrict__ skipW,
                                         const float* __restrict__ b,
                                         float (*sh)[DD])
{
    float num = g_num[n * DD + lane];
    float den = g_den[n * H + lane / F];
    float v = num / (den + 1e-16f);
    float skip = 0.f;
#pragma unroll
    for (int k = 0; k < DD; k++)
        skip += sh[sub][k] * skipW[k * DD + lane];
    v += skip + b[lane];
    return v > 0.f ? v : (__expf(v) - 1.f);    // ELU
}

// ==========================================================================
// K1: PE table + node embedding + proj/scores for layer 0.
// ==========================================================================
__global__ void __launch_bounds__(256)
k_first(const float* __restrict__ node_f, const float* __restrict__ b_val,
        const float* __restrict__ W_sta, const float* __restrict__ b_sta,
        const float* __restrict__ ada,
        const float* __restrict__ W, const float* __restrict__ as_,
        const float* __restrict__ at_)
{
    __shared__ float sh[4][DD];
    __shared__ float sp[4][DD];
    int tid  = threadIdx.x;
    int sub  = tid >> 6;
    int lane = tid & 63;
    int n    = blockIdx.x * 4 + sub;
    bool act = n < NN;

    // PE table (77*256 = 19712 >= 18432 elements)
    int idx = blockIdx.x * 256 + tid;
    if (idx < TT * DD) {
        int t = idx >> 6, d = idx & 63;
        float freq = __expf((float)(d & ~1) * (-9.210340371976184f / 64.0f));
        float s, c;
        __sincosf((float)t * freq, &s, &c);
        g_c[idx] = ((d & 1) ? c : s) + b_val[d];
    }

    if (act) {
        float acc = b_sta[lane] + ada[n * DD + lane];
#pragma unroll
        for (int k = 0; k < 32; k++)
            acc += node_f[n * 32 + k] * W_sta[k * DD + lane];
        sh[sub][lane] = acc;
        g_h[n * DD + lane] = acc;
    }
    __syncthreads();

    proj<8, 8>(act, n, sub, lane, W, as_, at_, sh, sp);
}

// ==========================================================================
// K3/K5: finalize layer L (ELU, projected skip), then proj for layer L+1.
// ==========================================================================
template<int HO, int FO>
__global__ void __launch_bounds__(256)
k_mid(const float* __restrict__ skipW, const float* __restrict__ b,
      const float* __restrict__ W, const float* __restrict__ as_,
      const float* __restrict__ at_)
{
    __shared__ float sh[4][DD];
    __shared__ float sp[4][DD];
    int tid  = threadIdx.x;
    int sub  = tid >> 6;
    int lane = tid & 63;
    int n    = blockIdx.x * 4 + sub;
    bool act = n < NN;

    if (act) sh[sub][lane] = g_h[n * DD + lane];
    __syncthreads();

    float v = 0.f;
    if (act) v = fin_val<8, 8>(n, sub, lane, skipW, b, sh);
    __syncthreads();
    if (act) {
        sh[sub][lane] = v;
        g_h[n * DD + lane] = v;       // layer-(L+1) input (identity skip source for L2)
    }
    __syncthreads();

    proj<HO, FO>(act, n, sub, lane, W, as_, at_, sh, sp);
}

// ==========================================================================
// Edge kernel, (e,d) granularity — best measured form (R6: 5.76us, occ 92%).
// Warp spans 32 consecutive d of ONE edge: ei/ss/st loads are warp-uniform
// broadcasts, p[s*64+d] is a coalesced 128B line. Max parallelism (314K thr).
// Max-subtraction dropped (activations O(0.1): exp cannot overflow;
// identical math — validated rel_err ~1e-6 since R2).
// ==========================================================================
template<int H, int F>
__global__ void __launch_bounds__(256)
k_edge(const int* __restrict__ ei)
{
    int idx = blockIdx.x * 256 + threadIdx.x;
    if (idx >= EE * DD) return;
    int e = idx >> 6;
    int d = idx & 63;
    int h = d / F;
    int s = __ldg(&ei[e]);
    int t = __ldg(&ei[EE + e]);
    float ev = g_ss[s * H + h] + g_st[t * H + h];
    ev = ev > 0.f ? ev : 0.2f * ev;
    float w = __expf(ev);
    if ((d % F) == 0) atomicAdd(&g_den[t * H + h], w);
    atomicAdd(&g_num[t * DD + d], w * g_p[s * DD + d]);
}

// ==========================================================================
// Big broadcast kernel, with layer-2 finalize fused into the prologue:
//   h[n,dq] = num/(den+eps) + h_prev + b2      (identity skip, no ELU)
//   out[bt,n,dq] = x[bt,n]*W[dq] + c[t,dq] + h[n,dq]
// Thread owns one (n,dq) column; h/W in registers; streaming stores.
// ==========================================================================
__global__ void __launch_bounds__(256)
k_big(const float* __restrict__ x, const float* __restrict__ Wv,
      const float* __restrict__ b2, float4* __restrict__ out)
{
    int col  = blockIdx.x * 256 + threadIdx.x;   // n*16 + dq, 0..4911
    if (col >= NN * 16) return;
    int dq   = col & 15;
    int n    = col >> 4;

    // fused layer-2 finalize (identity skip, + b2, no ELU)
    float4 num = ((const float4*)g_num)[col];
    float  den = g_den[n] + 1e-16f;
    float4 hp  = ((const float4*)g_h)[col];
    float4 bb  = ((const float4*)b2)[dq];
    float4 hh;
    hh.x = num.x / den + hp.x + bb.x;
    hh.y = num.y / den + hp.y + bb.y;
    hh.z = num.z / den + hp.z + bb.z;
    hh.w = num.w / den + hp.w + bb.w;

    float4 w = ((const float4*)Wv)[dq];

    int bt0 = blockIdx.y * CH;
    int t0  = bt0 % TT;          // CH | TT: no wrap inside chunk

#pragma unroll 4
    for (int i = 0; i < CH; i++) {
        int bt = bt0 + i;
        float  xv = __ldg(&x[bt * NN + n]);
        float4 cc = ((const float4*)g_c)[(t0 + i) * 16 + dq];
        float4 o;
        o.x = fmaf(xv, w.x, cc.x + hh.x);
        o.y = fmaf(xv, w.y, cc.y + hh.y);
        o.z = fmaf(xv, w.z, cc.z + hh.z);
        o.w = fmaf(xv, w.w, cc.w + hh.w);
        __stcs(&out[bt * (NN * 16) + col], o);   // streaming: don't pollute L2
    }
}

extern "C" void kernel_launch(void* const* d_in, const int* in_sizes, int n_in,
                              void* d_out, int out_size)
{
    const float* x       = (const float*)d_in[0];
    const float* node_f  = (const float*)d_in[1];
    const int*   ei      = (const int*)d_in[2];
    // d_in[3] edge_prob unused
    const float* W_val   = (const float*)d_in[4];
    const float* b_val   = (const float*)d_in[5];
    const float* W_sta   = (const float*)d_in[6];
    const float* b_sta   = (const float*)d_in[7];
    const float* ada     = (const float*)d_in[8];
    const float* g0W     = (const float*)d_in[9];
    const float* g0as    = (const float*)d_in[10];
    const float* g0at    = (const float*)d_in[11];
    const float* g0b     = (const float*)d_in[12];
    const float* g1W     = (const float*)d_in[13];
    const float* g1as    = (const float*)d_in[14];
    const float* g1at    = (const float*)d_in[15];
    const float* g1b     = (const float*)d_in[16];
    const float* g2W     = (const float*)d_in[17];
    const float* g2as    = (const float*)d_in[18];
    const float* g2at    = (const float*)d_in[19];
    const float* g2b     = (const float*)d_in[20];
    const float* g0skip  = (const float*)d_in[21];
    const float* g1skip  = (const float*)d_in[22];

    const int EB = (EE * DD + 255) / 256;   // 1228 blocks: max edge parallelism

    // GAT chain: 6 launches + fused layer-2 finalize inside k_big
    k_first<<<NODE_BLOCKS, 256>>>(node_f, b_val, W_sta, b_sta, ada, g0W, g0as, g0at);
    k_edge<8, 8><<<EB, 256>>>(ei);
    k_mid<8, 8><<<NODE_BLOCKS, 256>>>(g0skip, g0b, g1W, g1as, g1at);
    k_edge<8, 8><<<EB, 256>>>(ei);
    k_mid<1, 64><<<NODE_BLOCKS, 256>>>(g1skip, g1b, g2W, g2as, g2at);
    k_edge<1, 64><<<EB, 256>>>(ei);

    // Broadcast add (HBM-store-bound) + layer-2 finalize
    dim3 gb((NN * 16 + 255) / 256, (BB * TT) / CH);   // (20, 96)
    k_big<<<gb, 256>>>(x, W_val, g2b, (float4*)d_out);
}

// round 16
// speedup vs baseline: 1.9065x; 1.0842x over previous
#include <cuda_runtime.h>

#define NN 307
#define DD 64
#define EE 4912
#define TT 288
#define BB 8
#define NODE_BLOCKS 77      // 77*4 = 308 >= 307 nodes, single wave
#define CH 24               // bt-chunk per k_big block (24 | 288: never crosses b)

// ---- scratch (device globals; no allocation allowed) ----
__device__ float g_h[NN * DD];      // layer activations (node-private between kernels)
__device__ float g_p[NN * DD];      // projected features p = h @ W
__device__ float g_ss[NN * 8];      // per-node src scores
__device__ float g_st[NN * 8];      // per-node tgt scores
__device__ float g_num[NN * DD];    // softmax-weighted numerator accum
__device__ float g_den[NN * 8];     // softmax denominator accum
__device__ float g_c[TT * DD];      // pe[t,d] + b_val[d]

// ==========================================================================
// Per-node building blocks. Block = 256 threads = 4 nodes (sub, lane).
// ==========================================================================
template<int H, int F>
__device__ __forceinline__ void proj(bool act, int n, int sub, int lane,
                                     const float* __restrict__ W,
                                     const float* __restrict__ as_,
                                     const float* __restrict__ at_,
                                     float (*sh)[DD], float (*sp)[DD])
{
    if (act) {
        float p = 0.f;
#pragma unroll
        for (int k = 0; k < DD; k++)
            p += sh[sub][k] * W[k * DD + lane];
        g_p[n * DD + lane]   = p;
        g_num[n * DD + lane] = 0.f;
        sp[sub][lane] = p;
    }
    __syncthreads();
    if (act && lane < H) {
        float ssv = 0.f, stv = 0.f;
#pragma unroll
        for (int f = 0; f < F; f++) {
            float v = sp[sub][lane * F + f];
            ssv += v * as_[lane * F + f];
            stv += v * at_[lane * F + f];
        }
        g_ss[n * H + lane]  = ssv;
        g_st[n * H + lane]  = stv;
        g_den[n * H + lane] = 0.f;
    }
}

template<int H, int F>
__device__ __forceinline__ float fin_val(int n, int sub, int lane,
                                         const float* __restrict__ skipW,
                                         const float* __restrict__ b,
                                         float (*sh)[DD])
{
    float num = g_num[n * DD + lane];
    float den = g_den[n * H + lane / F];
    float v = num / (den + 1e-16f);
    float skip = 0.f;
#pragma unroll
    for (int k = 0; k < DD; k++)
        skip += sh[sub][k] * skipW[k * DD + lane];
    v += skip + b[lane];
    return v > 0.f ? v : (__expf(v) - 1.f);    // ELU
}

// ==========================================================================
// K1: PE table + node embedding + proj/scores for layer 0. (No gridsync:
// first kernel in the chain; inputs written before graph replay.)
// ==========================================================================
__global__ void __launch_bounds__(256)
k_first(const float* __restrict__ node_f, const float* __restrict__ b_val,
        const float* __restrict__ W_sta, const float* __restrict__ b_sta,
        const float* __restrict__ ada,
        const float* __restrict__ W, const float* __restrict__ as_,
        const float* __restrict__ at_)
{
    __shared__ float sh[4][DD];
    __shared__ float sp[4][DD];
    int tid  = threadIdx.x;
    int sub  = tid >> 6;
    int lane = tid & 63;
    int n    = blockIdx.x * 4 + sub;
    bool act = n < NN;

    // PE table (77*256 = 19712 >= 18432 elements)
    int idx = blockIdx.x * 256 + tid;
    if (idx < TT * DD) {
        int t = idx >> 6, d = idx & 63;
        float freq = __expf((float)(d & ~1) * (-9.210340371976184f / 64.0f));
        float s, c;
        __sincosf((float)t * freq, &s, &c);
        g_c[idx] = ((d & 1) ? c : s) + b_val[d];
    }

    if (act) {
        float acc = b_sta[lane] + ada[n * DD + lane];
#pragma unroll
        for (int k = 0; k < 32; k++)
            acc += node_f[n * 32 + k] * W_sta[k * DD + lane];
        sh[sub][lane] = acc;
        g_h[n * DD + lane] = acc;
    }
    __syncthreads();

    proj<8, 8>(act, n, sub, lane, W, as_, at_, sh, sp);
}

// ==========================================================================
// K3/K5: finalize layer L (ELU, projected skip), then proj for layer L+1.
// ==========================================================================
template<int HO, int FO>
__global__ void __launch_bounds__(256)
k_mid(const float* __restrict__ skipW, const float* __restrict__ b,
      const float* __restrict__ W, const float* __restrict__ as_,
      const float* __restrict__ at_)
{
    cudaGridDependencySynchronize();      // predecessor (edge) results visible

    __shared__ float sh[4][DD];
    __shared__ float sp[4][DD];
    int tid  = threadIdx.x;
    int sub  = tid >> 6;
    int lane = tid & 63;
    int n    = blockIdx.x * 4 + sub;
    bool act = n < NN;

    if (act) sh[sub][lane] = g_h[n * DD + lane];
    __syncthreads();

    float v = 0.f;
    if (act) v = fin_val<8, 8>(n, sub, lane, skipW, b, sh);
    __syncthreads();
    if (act) {
        sh[sub][lane] = v;
        g_h[n * DD + lane] = v;       // layer-(L+1) input (identity skip source for L2)
    }
    __syncthreads();

    proj<HO, FO>(act, n, sub, lane, W, as_, at_, sh, sp);
}

// ==========================================================================
// Edge kernel, (e,d) granularity, TWO edges per thread for ILP:
// warp-uniform ei/ss/st loads, coalesced p loads; the two edges' dependent
// chains are independent -> 2x memory-level parallelism per warp at still-
// high occupancy (614 blocks, 157K threads).
// Max-subtraction dropped (activations O(0.1): exp cannot overflow;
// identical math — validated rel_err ~1e-6 since R2).
// ==========================================================================
template<int H, int F>
__global__ void __launch_bounds__(256)
k_edge(const int* __restrict__ ei)
{
    cudaGridDependencySynchronize();      // predecessor (proj) results visible

    int idx = blockIdx.x * 256 + threadIdx.x;
    if (idx >= (EE / 2) * DD) return;
    int e0 = idx >> 6;
    int d  = idx & 63;
    int e1 = e0 + EE / 2;
    int h  = d / F;

    int s0 = __ldg(&ei[e0]), t0 = __ldg(&ei[EE + e0]);
    int s1 = __ldg(&ei[e1]), t1 = __ldg(&ei[EE + e1]);
    float ev0 = g_ss[s0 * H + h] + g_st[t0 * H + h];
    float ev1 = g_ss[s1 * H + h] + g_st[t1 * H + h];
    float p0 = g_p[s0 * DD + d];
    float p1 = g_p[s1 * DD + d];
    ev0 = ev0 > 0.f ? ev0 : 0.2f * ev0;
    ev1 = ev1 > 0.f ? ev1 : 0.2f * ev1;
    float w0 = __expf(ev0);
    float w1 = __expf(ev1);
    if ((d % F) == 0) {
        atomicAdd(&g_den[t0 * H + h], w0);
        atomicAdd(&g_den[t1 * H + h], w1);
    }
    atomicAdd(&g_num[t0 * DD + d], w0 * p0);
    atomicAdd(&g_num[t1 * DD + d], w1 * p1);
}

// ==========================================================================
// Big broadcast kernel, with layer-2 finalize fused into the prologue:
//   h[n,dq] = num/(den+eps) + h_prev + b2      (identity skip, no ELU)
//   out[bt,n,dq] = x[bt,n]*W[dq] + c[t,dq] + h[n,dq]
// Thread owns one (n,dq) column; h/W in registers; streaming stores.
// ==========================================================================
__global__ void __launch_bounds__(256)
k_big(const float* __restrict__ x, const float* __restrict__ Wv,
      const float* __restrict__ b2, float4* __restrict__ out)
{
    cudaGridDependencySynchronize();      // final edge results visible

    int col  = blockIdx.x * 256 + threadIdx.x;   // n*16 + dq, 0..4911
    if (col >= NN * 16) return;
    int dq   = col & 15;
    int n    = col >> 4;

    // fused layer-2 finalize (identity skip, + b2, no ELU)
    float4 num = ((const float4*)g_num)[col];
    float  den = g_den[n] + 1e-16f;
    float4 hp  = ((const float4*)g_h)[col];
    float4 bb  = ((const float4*)b2)[dq];
    float4 hh;
    hh.x = num.x / den + hp.x + bb.x;
    hh.y = num.y / den + hp.y + bb.y;
    hh.z = num.z / den + hp.z + bb.z;
    hh.w = num.w / den + hp.w + bb.w;

    float4 w = ((const float4*)Wv)[dq];

    int bt0 = blockIdx.y * CH;
    int t0  = bt0 % TT;          // CH | TT: no wrap inside chunk

#pragma unroll 4
    for (int i = 0; i < CH; i++) {
        int bt = bt0 + i;
        float  xv = __ldg(&x[bt * NN + n]);
        float4 cc = ((const float4*)g_c)[(t0 + i) * 16 + dq];
        float4 o;
        o.x = fmaf(xv, w.x, cc.x + hh.x);
        o.y = fmaf(xv, w.y, cc.y + hh.y);
        o.z = fmaf(xv, w.z, cc.z + hh.z);
        o.w = fmaf(xv, w.w, cc.w + hh.w);
        __stcs(&out[bt * (NN * 16) + col], o);   // streaming: don't pollute L2
    }
}

// --------------------------------------------------------------------------
// PDL launch helper: programmatic stream serialization lets the next
// kernel's CTAs schedule while the predecessor drains; the consumer-side
// cudaGridDependencySynchronize() provides the data-visibility guarantee.
// --------------------------------------------------------------------------
static inline void launch_pdl(const void* func, dim3 grid, dim3 block, void** args)
{
    cudaLaunchConfig_t cfg = {};
    cfg.gridDim  = grid;
    cfg.blockDim = block;
    cfg.stream   = 0;
    cudaLaunchAttribute attr[1];
    attr[0].id = cudaLaunchAttributeProgrammaticStreamSerialization;
    attr[0].val.programmaticStreamSerializationAllowed = 1;
    cfg.attrs    = attr;
    cfg.numAttrs = 1;
    cudaLaunchKernelExC(&cfg, func, args);
}

extern "C" void kernel_launch(void* const* d_in, const int* in_sizes, int n_in,
                              void* d_out, int out_size)
{
    const float* x       = (const float*)d_in[0];
    const float* node_f  = (const float*)d_in[1];
    const int*   ei      = (const int*)d_in[2];
    // d_in[3] edge_prob unused
    const float* W_val   = (const float*)d_in[4];
    const float* b_val   = (const float*)d_in[5];
    const float* W_sta   = (const float*)d_in[6];
    const float* b_sta   = (const float*)d_in[7];
    const float* ada     = (const float*)d_in[8];
    const float* g0W     = (const float*)d_in[9];
    const float* g0as    = (const float*)d_in[10];
    const float* g0at    = (const float*)d_in[11];
    const float* g0b     = (const float*)d_in[12];
    const float* g1W     = (const float*)d_in[13];
    const float* g1as    = (const float*)d_in[14];
    const float* g1at    = (const float*)d_in[15];
    const float* g1b     = (const float*)d_in[16];
    const float* g2W     = (const float*)d_in[17];
    const float* g2as    = (const float*)d_in[18];
    const float* g2at    = (const float*)d_in[19];
    const float* g2b     = (const float*)d_in[20];
    const float* g0skip  = (const float*)d_in[21];
    const float* g1skip  = (const float*)d_in[22];

    const int EB = ((EE / 2) * DD + 255) / 256;       // 614 blocks, 2 edges/thread
    float4* out = (float4*)d_out;

    // K1 (no PDL needed on the first kernel)
    k_first<<<NODE_BLOCKS, 256>>>(node_f, b_val, W_sta, b_sta, ada, g0W, g0as, g0at);

    {   // edge L0
        void* a[] = { (void*)&ei };
        launch_pdl((const void*)k_edge<8, 8>, dim3(EB), dim3(256), a);
    }
    {   // fin L0 + proj L1
        void* a[] = { (void*)&g0skip, (void*)&g0b, (void*)&g1W, (void*)&g1as, (void*)&g1at };
        launch_pdl((const void*)k_mid<8, 8>, dim3(NODE_BLOCKS), dim3(256), a);
    }
    {   // edge L1
        void* a[] = { (void*)&ei };
        launch_pdl((const void*)k_edge<8, 8>, dim3(EB), dim3(256), a);
    }
    {   // fin L1 + proj L2
        void* a[] = { (void*)&g1skip, (void*)&g1b, (void*)&g2W, (void*)&g2as, (void*)&g2at };
        launch_pdl((const void*)k_mid<1, 64>, dim3(NODE_BLOCKS), dim3(256), a);
    }
    {   // edge L2
        void* a[] = { (void*)&ei };
        launch_pdl((const void*)k_edge<1, 64>, dim3(EB), dim3(256), a);
    }
    {   // fused layer-2 finalize + broadcast add
        void* a[] = { (void*)&x, (void*)&W_val, (void*)&g2b, (void*)&out };
        launch_pdl((const void*)k_big,
                   dim3((NN * 16 + 255) / 256, (BB * TT) / CH), dim3(256), a);
    }
}